// round 7
// baseline (speedup 1.0000x reference)
#include <cuda_runtime.h>
#include <math.h>
#include <stdint.h>

#define KDIM     4096
#define NJ       24             // 4 pre + 4 post + 16 res
#define MM       128            // rows per CTA
#define BLOCK    256
#define KC       32             // k per chunk
#define NC       (KDIM / KC)    // 128 chunks
#define XSTR     36             // floats per staged row (36 % 32 == 4 -> conflict-free frags)
#define STAGEF   ((MM + NJ) * XSTR)        // floats per stage = 5472
#define WOFF     (MM * XSTR)               // weights offset inside stage (floats)
#define NSTG     5
#define SMEM_BYTES (NSTG * STAGEF * 4)     // 109440 B
#define SDSTR    28             // epilogue transpose stride
#define RMS_EPS  1.1920928955078125e-07f
#define SK_EPS   1e-6f

__device__ __align__(16) float g_Wt[NJ * KDIM];   // j-major, k contiguous, pre-scaled

// ---------------- helpers ----------------
__device__ __forceinline__ uint32_t smem_u32(const void* p) {
    return (uint32_t)__cvta_generic_to_shared(p);
}
__device__ __forceinline__ void cp16cg(uint32_t dst, const void* src) {
    asm volatile("cp.async.cg.shared.global [%0], [%1], 16;" :: "r"(dst), "l"(src));
}
__device__ __forceinline__ void cp16ca(uint32_t dst, const void* src) {
    asm volatile("cp.async.ca.shared.global [%0], [%1], 16;" :: "r"(dst), "l"(src));
}
__device__ __forceinline__ void cp_commit() { asm volatile("cp.async.commit_group;"); }
template <int N> __device__ __forceinline__ void cp_wait() {
    asm volatile("cp.async.wait_group %0;" :: "n"(N));
}
__device__ __forceinline__ void mma_tf32(float d[4],
                                         uint32_t a0, uint32_t a1, uint32_t a2, uint32_t a3,
                                         uint32_t b0, uint32_t b1) {
    asm volatile("mma.sync.aligned.m16n8k8.row.col.f32.tf32.tf32.f32 "
                 "{%0,%1,%2,%3}, {%4,%5,%6,%7}, {%8,%9}, {%0,%1,%2,%3};"
                 : "+f"(d[0]), "+f"(d[1]), "+f"(d[2]), "+f"(d[3])
                 : "r"(a0), "r"(a1), "r"(a2), "r"(a3), "r"(b0), "r"(b1));
}
__device__ __forceinline__ uint32_t f2u(float f) { return __float_as_uint(f); }

__global__ void prep_kernel(const float* __restrict__ norm_w,
                            const float* __restrict__ W_pre,
                            const float* __restrict__ W_post,
                            const float* __restrict__ W_res,
                            const float* __restrict__ a_pre,
                            const float* __restrict__ a_post,
                            const float* __restrict__ a_res) {
    int idx = blockIdx.x * blockDim.x + threadIdx.x;
    if (idx >= NJ * KDIM) return;
    int j = idx / KDIM;
    int k = idx - j * KDIM;
    float w, a;
    if (j < 4)      { w = W_pre [j * KDIM + k];       a = a_pre[0];  }
    else if (j < 8) { w = W_post[(j - 4) * KDIM + k]; a = a_post[0]; }
    else            { w = W_res [(j - 8) * KDIM + k]; a = a_res[0];  }
    g_Wt[j * KDIM + k] = w * a * norm_w[k];
}

__global__ __launch_bounds__(BLOCK, 2)
void mhc_mma_kernel(const float* __restrict__ x,
                    const float* __restrict__ b_pre,
                    const float* __restrict__ b_post,
                    const float* __restrict__ b_res,
                    float* __restrict__ out, int Btot) {
    extern __shared__ float dsm[];
    __shared__ float ssqp[BLOCK];

    const int tid  = threadIdx.x;
    const int lane = tid & 31;
    const int warp = tid >> 5;
    const int g    = lane >> 2;       // groupID
    const int c4   = lane & 3;        // threadID_in_group
    const int rowbase = blockIdx.x * MM;

    // ---- async chunk loader ----
    const float* xrow = x + (size_t)rowbase * KDIM;
    const uint32_t sbase = smem_u32(dsm);
    auto issue_chunk = [&](int c) {
        const int s = c % NSTG;
        const uint32_t ab = sbase + s * (STAGEF * 4);
        const float* xb = xrow + c * KC;
#pragma unroll
        for (int i = 0; i < 4; i++) {            // 1024 cp16 for x, 4/thread
            int idx = i * BLOCK + tid;
            int r = idx >> 3, u = idx & 7;
            cp16cg(ab + r * (XSTR * 4) + u * 16,
                   xb + (size_t)r * KDIM + u * 4);
        }
        if (tid < NJ * 8) {                      // 192 cp16 for W
            int j = tid >> 3, u = tid & 7;
            cp16ca(ab + WOFF * 4 + j * (XSTR * 4) + u * 16,
                   g_Wt + (size_t)j * KDIM + c * KC + u * 4);
        }
        cp_commit();
    };

    issue_chunk(0); issue_chunk(1); issue_chunk(2); issue_chunk(3);

    // D accumulators: [ntile][4] (one m16 tile per warp)
    float d[3][4];
#pragma unroll
    for (int n = 0; n < 3; n++)
#pragma unroll
        for (int q = 0; q < 4; q++) d[n][q] = 0.0f;

    // per-thread fragment offsets (floats, within stage)
    const int m0 = warp * 16;
    const int aof0 = (m0 + g) * XSTR + c4;            // row g
    const int aof1 = aof0 + 8 * XSTR;                 // row g+8
    const int bof0 = WOFF + (0 + g) * XSTR + c4;
    const int bof1 = WOFF + (8 + g) * XSTR + c4;
    const int bof2 = WOFF + (16 + g) * XSTR + c4;

    const int r_ssq = tid >> 1;                       // ssq: 2 threads per row
    const int h_ssq = (tid & 1) * 4;                  // float4 index offset

    float ssq = 0.0f;

    for (int c = 0; c < NC; ++c) {
        const int rem = NC - 1 - c;
        if (rem >= 3) cp_wait<3>();
        else if (rem == 2) cp_wait<2>();
        else if (rem == 1) cp_wait<1>();
        else cp_wait<0>();
        __syncthreads();                          // chunk c resident; c-1 fully consumed
        if (c + 4 < NC) issue_chunk(c + 4);       // reuses buffer of c-1 (safe post-barrier)

        const float* fs = dsm + (c % NSTG) * STAGEF;

        // ssq: 2 threads per row, 16 floats each (exact fp32)
        {
            const float4* xr = (const float4*)(fs + r_ssq * XSTR) + h_ssq;
#pragma unroll
            for (int i = 0; i < 4; i++) {
                float4 v = xr[i];
                ssq += v.x * v.x + v.y * v.y + v.z * v.z + v.w * v.w;
            }
        }

        // MMA: 4 k8-steps, 1 m-tile x 3 n-tiles
#pragma unroll
        for (int ks = 0; ks < 4; ks++) {
            const int k0 = ks * 8;
            uint32_t A[4];
            A[0] = f2u(fs[aof0 + k0]);     A[1] = f2u(fs[aof1 + k0]);
            A[2] = f2u(fs[aof0 + k0 + 4]); A[3] = f2u(fs[aof1 + k0 + 4]);
            uint32_t b0, b1;
            b0 = f2u(fs[bof0 + k0]); b1 = f2u(fs[bof0 + k0 + 4]);
            mma_tf32(d[0], A[0], A[1], A[2], A[3], b0, b1);
            b0 = f2u(fs[bof1 + k0]); b1 = f2u(fs[bof1 + k0 + 4]);
            mma_tf32(d[1], A[0], A[1], A[2], A[3], b0, b1);
            b0 = f2u(fs[bof2 + k0]); b1 = f2u(fs[bof2 + k0 + 4]);
            mma_tf32(d[2], A[0], A[1], A[2], A[3], b0, b1);
        }
    }

    ssqp[tid] = ssq;
    __syncthreads();                              // all MMA/ssq reads done -> reuse dsm

    // transpose D through smem: sD[row][j], stride 28
    float* sD = dsm;
#pragma unroll
    for (int n = 0; n < 3; n++) {
        *(float2*)&sD[(m0 + g) * SDSTR + 8 * n + 2 * c4] =
            make_float2(d[n][0], d[n][1]);
        *(float2*)&sD[(m0 + 8 + g) * SDSTR + 8 * n + 2 * c4] =
            make_float2(d[n][2], d[n][3]);
    }
    __syncthreads();

    // epilogue: one row per thread (threads 0..127)
    if (tid < MM) {
        const int row = rowbase + tid;
        const float* a = &sD[tid * SDSTR];
        const float ssqr = ssqp[2 * tid] + ssqp[2 * tid + 1];
        const float rinv = rsqrtf(ssqr * (1.0f / (float)KDIM) + RMS_EPS);

        float4 o;
        {
            float p0 = rinv * a[0] + b_pre[0];
            float p1 = rinv * a[1] + b_pre[1];
            float p2 = rinv * a[2] + b_pre[2];
            float p3 = rinv * a[3] + b_pre[3];
            o.x = __fdividef(1.0f, 1.0f + __expf(-p0));
            o.y = __fdividef(1.0f, 1.0f + __expf(-p1));
            o.z = __fdividef(1.0f, 1.0f + __expf(-p2));
            o.w = __fdividef(1.0f, 1.0f + __expf(-p3));
            *(float4*)(out + (size_t)row * 4) = o;
        }
        {
            float p0 = rinv * a[4] + b_post[0];
            float p1 = rinv * a[5] + b_post[1];
            float p2 = rinv * a[6] + b_post[2];
            float p3 = rinv * a[7] + b_post[3];
            o.x = 2.0f * __fdividef(1.0f, 1.0f + __expf(-p0));
            o.y = 2.0f * __fdividef(1.0f, 1.0f + __expf(-p1));
            o.z = 2.0f * __fdividef(1.0f, 1.0f + __expf(-p2));
            o.w = 2.0f * __fdividef(1.0f, 1.0f + __expf(-p3));
            *(float4*)(out + (size_t)Btot * 4 + (size_t)row * 4) = o;
        }

        float M[16];
#pragma unroll
        for (int j = 0; j < 16; j++)
            M[j] = __expf(rinv * a[8 + j] + b_res[j]);
#pragma unroll 1
        for (int it = 0; it < 20; it++) {
#pragma unroll
            for (int r = 0; r < 4; r++) {
                float s = M[4*r] + M[4*r+1] + M[4*r+2] + M[4*r+3] + SK_EPS;
                float inv = __fdividef(1.0f, s);
                M[4*r] *= inv; M[4*r+1] *= inv; M[4*r+2] *= inv; M[4*r+3] *= inv;
            }
#pragma unroll
            for (int cq = 0; cq < 4; cq++) {
                float s = M[cq] + M[cq+4] + M[cq+8] + M[cq+12] + SK_EPS;
                float inv = __fdividef(1.0f, s);
                M[cq] *= inv; M[cq+4] *= inv; M[cq+8] *= inv; M[cq+12] *= inv;
            }
        }
        float* ro = out + (size_t)Btot * 8 + (size_t)row * 16;
#pragma unroll
        for (int q = 0; q < 4; q++) {
            o.x = M[4*q]; o.y = M[4*q+1]; o.z = M[4*q+2]; o.w = M[4*q+3];
            *(float4*)(ro + 4 * q) = o;
        }
    }
}

extern "C" void kernel_launch(void* const* d_in, const int* in_sizes, int n_in,
                              void* d_out, int out_size) {
    const float* x      = (const float*)d_in[0];
    const float* norm_w = (const float*)d_in[1];
    const float* W_pre  = (const float*)d_in[2];
    const float* W_post = (const float*)d_in[3];
    const float* W_res  = (const float*)d_in[4];
    const float* b_pre  = (const float*)d_in[5];
    const float* b_post = (const float*)d_in[6];
    const float* b_res  = (const float*)d_in[7];
    const float* a_pre  = (const float*)d_in[8];
    const float* a_post = (const float*)d_in[9];
    const float* a_res  = (const float*)d_in[10];

    const int Btot = in_sizes[0] / KDIM;

    cudaFuncSetAttribute(mhc_mma_kernel,
                         cudaFuncAttributeMaxDynamicSharedMemorySize,
                         SMEM_BYTES);

    prep_kernel<<<(NJ * KDIM + 255) / 256, 256>>>(norm_w, W_pre, W_post, W_res,
                                                  a_pre, a_post, a_res);
    mhc_mma_kernel<<<Btot / MM, BLOCK, SMEM_BYTES>>>(x, b_pre, b_post, b_res,
                                                     (float*)d_out, Btot);
}